// round 14
// baseline (speedup 1.0000x reference)
#include <cuda_runtime.h>
#include <cstdint>

#define NN 100000
#define EE 800000
#define IN_DIM 256
#define H 4
#define D 32
#define HD 128
#define SLOPE 0.2f
#define NC0 50048   // layer-0/1 chunk split (multiple of 128)

// ---------------- scratch (no allocations allowed) ----------------
__device__ float g_feat[NN * HD];     // layer-0 projected features
__device__ float g_feat2[NN * HD];    // layer-1 projected features
__device__ float g_h1[NN * HD];       // layer-0 output (residual for layer 1)
__device__ float g_el[NN * H];
__device__ float g_er[NN * H];
__device__ float g_el2[NN * H];
__device__ float g_er2[NN * H];
__device__ float g_w[EE * H];         // exp(score) in CSR order
__device__ int   g_deg[NN];           // zero at load; re-zeroed by scan3
__device__ int   g_rowptr[NN + 1];
__device__ int   g_cursor[NN];
__device__ int   g_partial[256];
__device__ int   g_csr_src[EE];
__device__ int   g_csr_eid[EE];

__device__ __forceinline__ float elu1(float x) {
    return x > 0.f ? x : expm1f(x);
}
__device__ __forceinline__ float tf32r(float x) {
    uint32_t u;
    asm("cvt.rna.tf32.f32 %0, %1;" : "=r"(u) : "f"(x));
    return __uint_as_float(u);
}
__device__ __forceinline__ float lrelu(float x) {
    return x > 0.f ? x : SLOPE * x;
}

// ================= CSR build =================
__global__ void count_deg_kernel(const int* __restrict__ ei) {
    int e = blockIdx.x * blockDim.x + threadIdx.x;
    if (e < EE) atomicAdd(&g_deg[ei[EE + e]], 1);
}

#define SCAN_BS 512
#define NBLK1 ((NN + SCAN_BS - 1) / SCAN_BS)   // 196

__global__ __launch_bounds__(SCAN_BS) void scan1_kernel() {
    __shared__ int s[SCAN_BS];
    int t = threadIdx.x;
    int i = blockIdx.x * SCAN_BS + t;
    int v = (i < NN) ? g_deg[i] : 0;
    s[t] = v;
    __syncthreads();
#pragma unroll
    for (int off = 1; off < SCAN_BS; off <<= 1) {
        int x = (t >= off) ? s[t - off] : 0;
        __syncthreads();
        s[t] += x;
        __syncthreads();
    }
    if (i < NN) g_rowptr[i] = s[t] - v;
    if (t == SCAN_BS - 1) g_partial[blockIdx.x] = s[t];
}

__global__ __launch_bounds__(256) void scan2_kernel() {
    __shared__ int s[256];
    int t = threadIdx.x;
    int v = (t < NBLK1) ? g_partial[t] : 0;
    s[t] = v;
    __syncthreads();
#pragma unroll
    for (int off = 1; off < 256; off <<= 1) {
        int x = (t >= off) ? s[t - off] : 0;
        __syncthreads();
        s[t] += x;
        __syncthreads();
    }
    if (t < NBLK1) g_partial[t] = s[t] - v;
}

__global__ __launch_bounds__(SCAN_BS) void scan3_kernel() {
    int t = threadIdx.x;
    int i = blockIdx.x * SCAN_BS + t;
    if (i < NN) {
        int r = g_rowptr[i] + g_partial[blockIdx.x];
        g_rowptr[i] = r;
        g_cursor[i] = r;
        g_deg[i] = 0;                        // re-zero for next replay
    }
    if (i == 0) g_rowptr[NN] = EE;
}

__global__ void fill_csr_kernel(const int* __restrict__ ei) {
    int e = blockIdx.x * blockDim.x + threadIdx.x;
    if (e >= EE) return;
    int s = ei[e], d = ei[EE + e];
    int pos = atomicAdd(&g_cursor[d], 1);
    g_csr_src[pos] = s;
    g_csr_eid[pos] = e;
}

// ========== TF32 tensor-core GEMM fused with attention dots ==========
// Processes rows [rbase, rbase + 128*gridDim.x) of C[M,128] = A @ B.
#define AS_S 20
#define BS_S 136

__global__ __launch_bounds__(256, 2) void sgemm_tf32(const float* __restrict__ A,
                                                     const float* __restrict__ B,
                                                     const float* __restrict__ al,
                                                     const float* __restrict__ ar,
                                                     float* __restrict__ C,
                                                     float* __restrict__ elo,
                                                     float* __restrict__ ero,
                                                     int M, int K, int rbase) {
    __shared__ float As[2][128][AS_S];
    __shared__ float Bs[2][16][BS_S];
    int tid = threadIdx.x;
    int lane = tid & 31;
    int wid = tid >> 5;
    int warp_m = wid & 1;
    int warp_n = wid >> 1;
    int block_row = rbase + blockIdx.x * 128;

    float c[4][4][4];
#pragma unroll
    for (int i = 0; i < 4; i++)
#pragma unroll
        for (int j = 0; j < 4; j++)
#pragma unroll
            for (int k = 0; k < 4; k++) c[i][j][k] = 0.f;

    int ar_r = tid >> 2;
    int ac = (tid & 3) * 4;
    int br = tid >> 5;
    int bc = (tid & 31) * 4;

    int gr0 = block_row + ar_r;
    int gr1 = gr0 + 64;
    bool v0 = gr0 < M, v1 = gr1 < M;
    const float* Ap0 = A + (size_t)gr0 * K;
    const float* Ap1 = A + (size_t)gr1 * K;

    int ntiles = K >> 4;
    float4 pa0, pa1, pb0, pb1;
    {
        pa0 = v0 ? *(const float4*)(Ap0 + ac) : make_float4(0, 0, 0, 0);
        pa1 = v1 ? *(const float4*)(Ap1 + ac) : make_float4(0, 0, 0, 0);
        pb0 = *(const float4*)(B + (size_t)br * 128 + bc);
        pb1 = *(const float4*)(B + (size_t)(br + 8) * 128 + bc);
        float* as0 = &As[0][ar_r][ac];
        as0[0] = tf32r(pa0.x); as0[1] = tf32r(pa0.y);
        as0[2] = tf32r(pa0.z); as0[3] = tf32r(pa0.w);
        float* as1 = &As[0][ar_r + 64][ac];
        as1[0] = tf32r(pa1.x); as1[1] = tf32r(pa1.y);
        as1[2] = tf32r(pa1.z); as1[3] = tf32r(pa1.w);
        float* bs0 = &Bs[0][br][bc];
        bs0[0] = tf32r(pb0.x); bs0[1] = tf32r(pb0.y);
        bs0[2] = tf32r(pb0.z); bs0[3] = tf32r(pb0.w);
        float* bs1 = &Bs[0][br + 8][bc];
        bs1[0] = tf32r(pb1.x); bs1[1] = tf32r(pb1.y);
        bs1[2] = tf32r(pb1.z); bs1[3] = tf32r(pb1.w);
    }
    __syncthreads();

    int buf = 0;
    for (int kt = 0; kt < ntiles; kt++) {
        bool more = (kt + 1) < ntiles;
        if (more) {
            int kb = (kt + 1) * 16;
            pa0 = v0 ? *(const float4*)(Ap0 + kb + ac) : make_float4(0, 0, 0, 0);
            pa1 = v1 ? *(const float4*)(Ap1 + kb + ac) : make_float4(0, 0, 0, 0);
            pb0 = *(const float4*)(B + (size_t)(kb + br) * 128 + bc);
            pb1 = *(const float4*)(B + (size_t)(kb + br + 8) * 128 + bc);
        }
#pragma unroll
        for (int ks = 0; ks < 2; ks++) {
            int k8 = ks * 8;
            uint32_t af[4][4];
            uint32_t bf[4][2];
#pragma unroll
            for (int mi = 0; mi < 4; mi++) {
                int r = warp_m * 64 + mi * 16 + (lane >> 2);
                int kc = k8 + (lane & 3);
                af[mi][0] = __float_as_uint(As[buf][r][kc]);
                af[mi][1] = __float_as_uint(As[buf][r + 8][kc]);
                af[mi][2] = __float_as_uint(As[buf][r][kc + 4]);
                af[mi][3] = __float_as_uint(As[buf][r + 8][kc + 4]);
            }
#pragma unroll
            for (int nj = 0; nj < 4; nj++) {
                int cc = warp_n * 32 + nj * 8 + (lane >> 2);
                int kr = k8 + (lane & 3);
                bf[nj][0] = __float_as_uint(Bs[buf][kr][cc]);
                bf[nj][1] = __float_as_uint(Bs[buf][kr + 4][cc]);
            }
#pragma unroll
            for (int mi = 0; mi < 4; mi++)
#pragma unroll
                for (int nj = 0; nj < 4; nj++) {
                    asm("mma.sync.aligned.m16n8k8.row.col.f32.tf32.tf32.f32 "
                        "{%0,%1,%2,%3}, {%4,%5,%6,%7}, {%8,%9}, {%0,%1,%2,%3};"
                        : "+f"(c[mi][nj][0]), "+f"(c[mi][nj][1]),
                          "+f"(c[mi][nj][2]), "+f"(c[mi][nj][3])
                        : "r"(af[mi][0]), "r"(af[mi][1]),
                          "r"(af[mi][2]), "r"(af[mi][3]),
                          "r"(bf[nj][0]), "r"(bf[nj][1]));
                }
        }
        if (more) {
            int nb = buf ^ 1;
            float* as0 = &As[nb][ar_r][ac];
            as0[0] = tf32r(pa0.x); as0[1] = tf32r(pa0.y);
            as0[2] = tf32r(pa0.z); as0[3] = tf32r(pa0.w);
            float* as1 = &As[nb][ar_r + 64][ac];
            as1[0] = tf32r(pa1.x); as1[1] = tf32r(pa1.y);
            as1[2] = tf32r(pa1.z); as1[3] = tf32r(pa1.w);
            float* bs0 = &Bs[nb][br][bc];
            bs0[0] = tf32r(pb0.x); bs0[1] = tf32r(pb0.y);
            bs0[2] = tf32r(pb0.z); bs0[3] = tf32r(pb0.w);
            float* bs1 = &Bs[nb][br + 8][bc];
            bs1[0] = tf32r(pb1.x); bs1[1] = tf32r(pb1.y);
            bs1[2] = tf32r(pb1.z); bs1[3] = tf32r(pb1.w);
        }
        __syncthreads();
        buf ^= 1;
    }

    float alv[8], arv[8];
#pragma unroll
    for (int nj = 0; nj < 4; nj++) {
#pragma unroll
        for (int t = 0; t < 2; t++) {
            int col = warp_n * 32 + nj * 8 + (lane & 3) * 2 + t;
            alv[nj * 2 + t] = al[col];
            arv[nj * 2 + t] = ar[col];
        }
    }

#pragma unroll
    for (int mi = 0; mi < 4; mi++) {
        float sl0 = 0.f, sl1 = 0.f, sr0 = 0.f, sr1 = 0.f;
#pragma unroll
        for (int nj = 0; nj < 4; nj++) {
            int row0 = block_row + warp_m * 64 + mi * 16 + (lane >> 2);
            int col = warp_n * 32 + nj * 8 + (lane & 3) * 2;
            if (row0 < M)
                *(float2*)(C + (size_t)row0 * 128 + col) =
                    make_float2(c[mi][nj][0], c[mi][nj][1]);
            int row1 = row0 + 8;
            if (row1 < M)
                *(float2*)(C + (size_t)row1 * 128 + col) =
                    make_float2(c[mi][nj][2], c[mi][nj][3]);
            sl0 += c[mi][nj][0] * alv[nj * 2] + c[mi][nj][1] * alv[nj * 2 + 1];
            sl1 += c[mi][nj][2] * alv[nj * 2] + c[mi][nj][3] * alv[nj * 2 + 1];
            sr0 += c[mi][nj][0] * arv[nj * 2] + c[mi][nj][1] * arv[nj * 2 + 1];
            sr1 += c[mi][nj][2] * arv[nj * 2] + c[mi][nj][3] * arv[nj * 2 + 1];
        }
#pragma unroll
        for (int o = 1; o <= 2; o <<= 1) {
            sl0 += __shfl_xor_sync(0xffffffffu, sl0, o);
            sl1 += __shfl_xor_sync(0xffffffffu, sl1, o);
            sr0 += __shfl_xor_sync(0xffffffffu, sr0, o);
            sr1 += __shfl_xor_sync(0xffffffffu, sr1, o);
        }
        if ((lane & 3) == 0) {
            int row0 = block_row + warp_m * 64 + mi * 16 + (lane >> 2);
            int row1 = row0 + 8;
            if (row0 < M) {
                elo[(size_t)row0 * 4 + warp_n] = sl0;
                ero[(size_t)row0 * 4 + warp_n] = sr0;
            }
            if (row1 < M) {
                elo[(size_t)row1 * 4 + warp_n] = sl1;
                ero[(size_t)row1 * 4 + warp_n] = sr1;
            }
        }
    }
}

// ------ warp-per-node: inline scores (lane-parallel) + w + agg ----------
// Processes nodes [base, base+cnt). pass 1: z from el[src]+er[node], write
// w/atten/(e1), accumulate denom. pass 2: unroll-4 weighted feat gather.
template <int LAYER>
__global__ __launch_bounds__(256) void node_agg_kernel(const float* __restrict__ feat,
                                                       const float* __restrict__ el,
                                                       const float* __restrict__ erp,
                                                       float* __restrict__ out,
                                                       float* __restrict__ atten,
                                                       float* __restrict__ e1,
                                                       int base, int cnt) {
    int node = base + blockIdx.x * 8 + (threadIdx.x >> 5);
    if (node >= base + cnt || node >= NN) return;
    int lane = threadIdx.x & 31;
    int beg = g_rowptr[node], end = g_rowptr[node + 1];
    float4 er = *(const float4*)(erp + (size_t)node * 4);

    // pass 1
    float4 s = make_float4(0.f, 0.f, 0.f, 0.f);
    for (int i = beg + lane; i < end; i += 32) {
        int src = g_csr_src[i];
        int eid = g_csr_eid[i];
        float4 l = *(const float4*)(el + (size_t)src * 4);
        float z0 = lrelu(l.x + er.x), z1 = lrelu(l.y + er.y);
        float z2 = lrelu(l.z + er.z), z3 = lrelu(l.w + er.w);
        atten[eid] = 0.25f * (z0 + z1 + z2 + z3);
        if (LAYER == 1)
            *(float4*)(e1 + (size_t)eid * 4) = make_float4(z0, z1, z2, z3);
        float4 wv = make_float4(__expf(z0), __expf(z1), __expf(z2), __expf(z3));
        *(float4*)(g_w + (size_t)i * 4) = wv;
        s.x += wv.x; s.y += wv.y; s.z += wv.z; s.w += wv.w;
    }
    __syncwarp();
#pragma unroll
    for (int o = 16; o; o >>= 1) {
        s.x += __shfl_xor_sync(0xffffffffu, s.x, o);
        s.y += __shfl_xor_sync(0xffffffffu, s.y, o);
        s.z += __shfl_xor_sync(0xffffffffu, s.z, o);
        s.w += __shfl_xor_sync(0xffffffffu, s.w, o);
    }

    int h = lane >> 3;
    float dh = (h == 0) ? s.x : (h == 1) ? s.y : (h == 2) ? s.z : s.w;
    float inv = dh > 0.f ? 1.f / dh : 0.f;

    // pass 2 (unroll 4 for MLP)
    float4 acc = make_float4(0.f, 0.f, 0.f, 0.f);
    int i = beg;
    for (; i + 4 <= end; i += 4) {
        int s0 = g_csr_src[i], s1 = g_csr_src[i + 1];
        int s2 = g_csr_src[i + 2], s3 = g_csr_src[i + 3];
        float a0 = g_w[(size_t)i * 4 + h] * inv;
        float a1 = g_w[(size_t)(i + 1) * 4 + h] * inv;
        float a2 = g_w[(size_t)(i + 2) * 4 + h] * inv;
        float a3 = g_w[(size_t)(i + 3) * 4 + h] * inv;
        float4 f0 = *(const float4*)(feat + (size_t)s0 * HD + lane * 4);
        float4 f1 = *(const float4*)(feat + (size_t)s1 * HD + lane * 4);
        float4 f2 = *(const float4*)(feat + (size_t)s2 * HD + lane * 4);
        float4 f3 = *(const float4*)(feat + (size_t)s3 * HD + lane * 4);
        acc.x += f0.x * a0 + f1.x * a1 + f2.x * a2 + f3.x * a3;
        acc.y += f0.y * a0 + f1.y * a1 + f2.y * a2 + f3.y * a3;
        acc.z += f0.z * a0 + f1.z * a1 + f2.z * a2 + f3.z * a3;
        acc.w += f0.w * a0 + f1.w * a1 + f2.w * a2 + f3.w * a3;
    }
    for (; i < end; i++) {
        int s0 = g_csr_src[i];
        float a0 = g_w[(size_t)i * 4 + h] * inv;
        float4 f0 = *(const float4*)(feat + (size_t)s0 * HD + lane * 4);
        acc.x += f0.x * a0; acc.y += f0.y * a0;
        acc.z += f0.z * a0; acc.w += f0.w * a0;
    }

    if (LAYER == 0) {
        acc.x = elu1(acc.x); acc.y = elu1(acc.y);
        acc.z = elu1(acc.z); acc.w = elu1(acc.w);
        *(float4*)(out + (size_t)node * HD + lane * 4) = acc;  // out = g_h1
    } else {
        float4 r = *(const float4*)(g_h1 + (size_t)node * HD + lane * 4);
        acc.x = elu1(acc.x + r.x); acc.y = elu1(acc.y + r.y);
        acc.z = elu1(acc.z + r.z); acc.w = elu1(acc.w + r.w);
        *(float4*)(out + (size_t)node * HD + lane * 4) = acc;  // temp [N,128]
        int d = (lane * 4) & 31;
        float* headp = out + (size_t)NN * HD + (size_t)h * NN * D + (size_t)node * D + d;
        *(float4*)headp = acc;
    }
}

static inline int cdiv(int a, int b) { return (a + b - 1) / b; }

extern "C" void kernel_launch(void* const* d_in, const int* in_sizes, int n_in,
                              void* d_out, int out_size) {
    const float* x   = (const float*)d_in[0];
    const int*   ei  = (const int*)d_in[1];
    const float* W0  = (const float*)d_in[2];
    const float* al0 = (const float*)d_in[3];
    const float* ar0 = (const float*)d_in[4];
    const float* W1  = (const float*)d_in[5];
    const float* al1 = (const float*)d_in[6];
    const float* ar1 = (const float*)d_in[7];
    float* out = (float*)d_out;

    float* e1_out = out + (size_t)NN * HD + (size_t)H * NN * D;  // [E, H]
    float* atten0 = e1_out + (size_t)EE * H;                     // [E]
    float* atten1 = atten0 + EE;                                 // [E]

    void *p_feat, *p_feat2, *p_h1, *p_el, *p_er, *p_el2, *p_er2;
    cudaGetSymbolAddress(&p_feat, g_feat);
    cudaGetSymbolAddress(&p_feat2, g_feat2);
    cudaGetSymbolAddress(&p_h1, g_h1);
    cudaGetSymbolAddress(&p_el, g_el);
    cudaGetSymbolAddress(&p_er, g_er);
    cudaGetSymbolAddress(&p_el2, g_el2);
    cudaGetSymbolAddress(&p_er2, g_er2);
    float* feat  = (float*)p_feat;
    float* feat2 = (float*)p_feat2;
    float* h1    = (float*)p_h1;
    float* el    = (float*)p_el;
    float* er    = (float*)p_er;
    float* el2   = (float*)p_el2;
    float* er2   = (float*)p_er2;

    const int T = 256;
    int g_edge = cdiv(EE, T);
    const int NC1 = NN - NC0;

    cudaStream_t sA;
    cudaStreamCreateWithFlags(&sA, cudaStreamNonBlocking);
    cudaEvent_t evFork, evCsr, evA0, evA1;
    cudaEventCreateWithFlags(&evFork, cudaEventDisableTiming);
    cudaEventCreateWithFlags(&evCsr, cudaEventDisableTiming);
    cudaEventCreateWithFlags(&evA0, cudaEventDisableTiming);
    cudaEventCreateWithFlags(&evA1, cudaEventDisableTiming);

    // ---- fork: CSR build on sA, concurrent with layer-0 GEMM ----
    cudaEventRecord(evFork, 0);
    cudaStreamWaitEvent(sA, evFork, 0);
    count_deg_kernel<<<g_edge, T, 0, sA>>>(ei);                              // 1
    scan1_kernel<<<NBLK1, SCAN_BS, 0, sA>>>();                               // 2
    scan2_kernel<<<1, 256, 0, sA>>>();                                       // 3
    sgemm_tf32<<<cdiv(NN, 128), T>>>(x, W0, al0, ar0, feat, el, er,
                                     NN, IN_DIM, 0);                         // 4 <- profiled
    scan3_kernel<<<NBLK1, SCAN_BS, 0, sA>>>();                               // 5
    fill_csr_kernel<<<g_edge, T, 0, sA>>>(ei);                               // 6
    cudaEventRecord(evCsr, sA);

    // ---- join: node_agg<0> chunk0 needs GEMM0 (main) + CSR (sA) ----
    cudaStreamWaitEvent(0, evCsr, 0);
    node_agg_kernel<0><<<cdiv(NC0, 8), T>>>(feat, el, er, h1,
                                            atten0, nullptr, 0, NC0);        // 7
    cudaEventRecord(evA0, 0);

    // ---- overlap: GEMM1 chunk0 (main) ∥ node_agg<0> chunk1 (sA) ----
    cudaStreamWaitEvent(sA, evA0, 0);
    node_agg_kernel<0><<<cdiv(NC1, 8), T, 0, sA>>>(feat, el, er, h1,
                                                   atten0, nullptr, NC0, NC1); // 8
    cudaEventRecord(evA1, sA);

    sgemm_tf32<<<NC0 / 128, T>>>(h1, W1, al1, ar1, feat2, el2, er2,
                                 NN, HD, 0);                                 // 9

    cudaStreamWaitEvent(0, evA1, 0);
    sgemm_tf32<<<cdiv(NC1, 128), T>>>(h1, W1, al1, ar1, feat2, el2, er2,
                                      NN, HD, NC0);                          // 10

    // ---- layer-1 aggregate (full) ----
    node_agg_kernel<1><<<cdiv(NN, 8), T>>>(feat2, el2, er2, out,
                                           atten1, e1_out, 0, NN);           // 11
}

// round 15
// speedup vs baseline: 1.3601x; 1.3601x over previous
#include <cuda_runtime.h>
#include <cstdint>

#define NN 100000
#define EE 800000
#define IN_DIM 256
#define H 4
#define D 32
#define HD 128
#define SLOPE 0.2f

// ---------------- scratch (no allocations allowed) ----------------
__device__ float g_feat[NN * HD];     // projected features of current layer
__device__ float g_h1[NN * HD];       // layer-0 output (residual for layer 1)
__device__ float g_el[NN * H];
__device__ float g_er[NN * H];
__device__ float g_w[EE * H];         // exp(score) in CSR order
__device__ int   g_deg[NN];           // zero at load; re-zeroed by scan3
__device__ int   g_rowptr[NN + 1];
__device__ int   g_cursor[NN];
__device__ int   g_partial[256];
__device__ int   g_csr_src[EE];
__device__ int   g_csr_eid[EE];

__device__ __forceinline__ float elu1(float x) {
    return x > 0.f ? x : expm1f(x);
}
__device__ __forceinline__ float tf32r(float x) {
    uint32_t u;
    asm("cvt.rna.tf32.f32 %0, %1;" : "=r"(u) : "f"(x));
    return __uint_as_float(u);
}
__device__ __forceinline__ float lrelu(float x) {
    return x > 0.f ? x : SLOPE * x;
}

// ================= CSR build =================
__global__ void count_deg_kernel(const int* __restrict__ ei) {
    int e = blockIdx.x * blockDim.x + threadIdx.x;
    if (e < EE) atomicAdd(&g_deg[ei[EE + e]], 1);
}

#define SCAN_BS 512
#define NBLK1 ((NN + SCAN_BS - 1) / SCAN_BS)   // 196

__global__ __launch_bounds__(SCAN_BS) void scan1_kernel() {
    __shared__ int s[SCAN_BS];
    int t = threadIdx.x;
    int i = blockIdx.x * SCAN_BS + t;
    int v = (i < NN) ? g_deg[i] : 0;
    s[t] = v;
    __syncthreads();
#pragma unroll
    for (int off = 1; off < SCAN_BS; off <<= 1) {
        int x = (t >= off) ? s[t - off] : 0;
        __syncthreads();
        s[t] += x;
        __syncthreads();
    }
    if (i < NN) g_rowptr[i] = s[t] - v;
    if (t == SCAN_BS - 1) g_partial[blockIdx.x] = s[t];
}

__global__ __launch_bounds__(256) void scan2_kernel() {
    __shared__ int s[256];
    int t = threadIdx.x;
    int v = (t < NBLK1) ? g_partial[t] : 0;
    s[t] = v;
    __syncthreads();
#pragma unroll
    for (int off = 1; off < 256; off <<= 1) {
        int x = (t >= off) ? s[t - off] : 0;
        __syncthreads();
        s[t] += x;
        __syncthreads();
    }
    if (t < NBLK1) g_partial[t] = s[t] - v;
}

__global__ __launch_bounds__(SCAN_BS) void scan3_kernel() {
    int t = threadIdx.x;
    int i = blockIdx.x * SCAN_BS + t;
    if (i < NN) {
        int r = g_rowptr[i] + g_partial[blockIdx.x];
        g_rowptr[i] = r;
        g_cursor[i] = r;
        g_deg[i] = 0;                        // re-zero for next replay
    }
    if (i == 0) g_rowptr[NN] = EE;
}

__global__ void fill_csr_kernel(const int* __restrict__ ei) {
    int e = blockIdx.x * blockDim.x + threadIdx.x;
    if (e >= EE) return;
    int s = ei[e], d = ei[EE + e];
    int pos = atomicAdd(&g_cursor[d], 1);
    g_csr_src[pos] = s;
    g_csr_eid[pos] = e;
}

// ========== TF32 tensor-core GEMM fused with attention dots (R12) =====
#define AS_S 20
#define BS_S 136

__global__ __launch_bounds__(256, 2) void sgemm_tf32(const float* __restrict__ A,
                                                     const float* __restrict__ B,
                                                     const float* __restrict__ al,
                                                     const float* __restrict__ ar,
                                                     float* __restrict__ C,
                                                     int M, int K) {
    __shared__ float As[2][128][AS_S];
    __shared__ float Bs[2][16][BS_S];
    int tid = threadIdx.x;
    int lane = tid & 31;
    int wid = tid >> 5;
    int warp_m = wid & 1;
    int warp_n = wid >> 1;
    int block_row = blockIdx.x * 128;

    float c[4][4][4];
#pragma unroll
    for (int i = 0; i < 4; i++)
#pragma unroll
        for (int j = 0; j < 4; j++)
#pragma unroll
            for (int k = 0; k < 4; k++) c[i][j][k] = 0.f;

    int ar_r = tid >> 2;
    int ac = (tid & 3) * 4;
    int br = tid >> 5;
    int bc = (tid & 31) * 4;

    int gr0 = block_row + ar_r;
    int gr1 = gr0 + 64;
    bool v0 = gr0 < M, v1 = gr1 < M;
    const float* Ap0 = A + (size_t)gr0 * K;
    const float* Ap1 = A + (size_t)gr1 * K;

    int ntiles = K >> 4;
    float4 pa0, pa1, pb0, pb1;
    {
        pa0 = v0 ? *(const float4*)(Ap0 + ac) : make_float4(0, 0, 0, 0);
        pa1 = v1 ? *(const float4*)(Ap1 + ac) : make_float4(0, 0, 0, 0);
        pb0 = *(const float4*)(B + (size_t)br * 128 + bc);
        pb1 = *(const float4*)(B + (size_t)(br + 8) * 128 + bc);
        float* as0 = &As[0][ar_r][ac];
        as0[0] = tf32r(pa0.x); as0[1] = tf32r(pa0.y);
        as0[2] = tf32r(pa0.z); as0[3] = tf32r(pa0.w);
        float* as1 = &As[0][ar_r + 64][ac];
        as1[0] = tf32r(pa1.x); as1[1] = tf32r(pa1.y);
        as1[2] = tf32r(pa1.z); as1[3] = tf32r(pa1.w);
        float* bs0 = &Bs[0][br][bc];
        bs0[0] = tf32r(pb0.x); bs0[1] = tf32r(pb0.y);
        bs0[2] = tf32r(pb0.z); bs0[3] = tf32r(pb0.w);
        float* bs1 = &Bs[0][br + 8][bc];
        bs1[0] = tf32r(pb1.x); bs1[1] = tf32r(pb1.y);
        bs1[2] = tf32r(pb1.z); bs1[3] = tf32r(pb1.w);
    }
    __syncthreads();

    int buf = 0;
    for (int kt = 0; kt < ntiles; kt++) {
        bool more = (kt + 1) < ntiles;
        if (more) {
            int kb = (kt + 1) * 16;
            pa0 = v0 ? *(const float4*)(Ap0 + kb + ac) : make_float4(0, 0, 0, 0);
            pa1 = v1 ? *(const float4*)(Ap1 + kb + ac) : make_float4(0, 0, 0, 0);
            pb0 = *(const float4*)(B + (size_t)(kb + br) * 128 + bc);
            pb1 = *(const float4*)(B + (size_t)(kb + br + 8) * 128 + bc);
        }
#pragma unroll
        for (int ks = 0; ks < 2; ks++) {
            int k8 = ks * 8;
            uint32_t af[4][4];
            uint32_t bf[4][2];
#pragma unroll
            for (int mi = 0; mi < 4; mi++) {
                int r = warp_m * 64 + mi * 16 + (lane >> 2);
                int kc = k8 + (lane & 3);
                af[mi][0] = __float_as_uint(As[buf][r][kc]);
                af[mi][1] = __float_as_uint(As[buf][r + 8][kc]);
                af[mi][2] = __float_as_uint(As[buf][r][kc + 4]);
                af[mi][3] = __float_as_uint(As[buf][r + 8][kc + 4]);
            }
#pragma unroll
            for (int nj = 0; nj < 4; nj++) {
                int cc = warp_n * 32 + nj * 8 + (lane >> 2);
                int kr = k8 + (lane & 3);
                bf[nj][0] = __float_as_uint(Bs[buf][kr][cc]);
                bf[nj][1] = __float_as_uint(Bs[buf][kr + 4][cc]);
            }
#pragma unroll
            for (int mi = 0; mi < 4; mi++)
#pragma unroll
                for (int nj = 0; nj < 4; nj++) {
                    asm("mma.sync.aligned.m16n8k8.row.col.f32.tf32.tf32.f32 "
                        "{%0,%1,%2,%3}, {%4,%5,%6,%7}, {%8,%9}, {%0,%1,%2,%3};"
                        : "+f"(c[mi][nj][0]), "+f"(c[mi][nj][1]),
                          "+f"(c[mi][nj][2]), "+f"(c[mi][nj][3])
                        : "r"(af[mi][0]), "r"(af[mi][1]),
                          "r"(af[mi][2]), "r"(af[mi][3]),
                          "r"(bf[nj][0]), "r"(bf[nj][1]));
                }
        }
        if (more) {
            int nb = buf ^ 1;
            float* as0 = &As[nb][ar_r][ac];
            as0[0] = tf32r(pa0.x); as0[1] = tf32r(pa0.y);
            as0[2] = tf32r(pa0.z); as0[3] = tf32r(pa0.w);
            float* as1 = &As[nb][ar_r + 64][ac];
            as1[0] = tf32r(pa1.x); as1[1] = tf32r(pa1.y);
            as1[2] = tf32r(pa1.z); as1[3] = tf32r(pa1.w);
            float* bs0 = &Bs[nb][br][bc];
            bs0[0] = tf32r(pb0.x); bs0[1] = tf32r(pb0.y);
            bs0[2] = tf32r(pb0.z); bs0[3] = tf32r(pb0.w);
            float* bs1 = &Bs[nb][br + 8][bc];
            bs1[0] = tf32r(pb1.x); bs1[1] = tf32r(pb1.y);
            bs1[2] = tf32r(pb1.z); bs1[3] = tf32r(pb1.w);
        }
        __syncthreads();
        buf ^= 1;
    }

    float alv[8], arv[8];
#pragma unroll
    for (int nj = 0; nj < 4; nj++) {
#pragma unroll
        for (int t = 0; t < 2; t++) {
            int col = warp_n * 32 + nj * 8 + (lane & 3) * 2 + t;
            alv[nj * 2 + t] = al[col];
            arv[nj * 2 + t] = ar[col];
        }
    }

#pragma unroll
    for (int mi = 0; mi < 4; mi++) {
        float sl0 = 0.f, sl1 = 0.f, sr0 = 0.f, sr1 = 0.f;
#pragma unroll
        for (int nj = 0; nj < 4; nj++) {
            int row0 = block_row + warp_m * 64 + mi * 16 + (lane >> 2);
            int col = warp_n * 32 + nj * 8 + (lane & 3) * 2;
            if (row0 < M)
                *(float2*)(C + (size_t)row0 * 128 + col) =
                    make_float2(c[mi][nj][0], c[mi][nj][1]);
            int row1 = row0 + 8;
            if (row1 < M)
                *(float2*)(C + (size_t)row1 * 128 + col) =
                    make_float2(c[mi][nj][2], c[mi][nj][3]);
            sl0 += c[mi][nj][0] * alv[nj * 2] + c[mi][nj][1] * alv[nj * 2 + 1];
            sl1 += c[mi][nj][2] * alv[nj * 2] + c[mi][nj][3] * alv[nj * 2 + 1];
            sr0 += c[mi][nj][0] * arv[nj * 2] + c[mi][nj][1] * arv[nj * 2 + 1];
            sr1 += c[mi][nj][2] * arv[nj * 2] + c[mi][nj][3] * arv[nj * 2 + 1];
        }
#pragma unroll
        for (int o = 1; o <= 2; o <<= 1) {
            sl0 += __shfl_xor_sync(0xffffffffu, sl0, o);
            sl1 += __shfl_xor_sync(0xffffffffu, sl1, o);
            sr0 += __shfl_xor_sync(0xffffffffu, sr0, o);
            sr1 += __shfl_xor_sync(0xffffffffu, sr1, o);
        }
        if ((lane & 3) == 0) {
            int row0 = block_row + warp_m * 64 + mi * 16 + (lane >> 2);
            int row1 = row0 + 8;
            if (row0 < M) {
                g_el[(size_t)row0 * 4 + warp_n] = sl0;
                g_er[(size_t)row0 * 4 + warp_n] = sr0;
            }
            if (row1 < M) {
                g_el[(size_t)row1 * 4 + warp_n] = sl1;
                g_er[(size_t)row1 * 4 + warp_n] = sr1;
            }
        }
    }
}

// ------ warp-per-node: inline scores (lane-parallel) + w + agg ----------
// pass 1 (lane-strided): z = lrelu(el[src]+er[node]); write w=exp(z),
// atten[eid], (layer1) e1[eid]; accumulate denom.
// pass 2 (warp-serial): unroll-4 weighted feat gather (MLP vs ~250cyc L2).
template <int LAYER>
__global__ __launch_bounds__(256) void node_agg_kernel(const float* __restrict__ feat,
                                                       float* __restrict__ out,
                                                       float* __restrict__ atten,
                                                       float* __restrict__ e1) {
    int node = blockIdx.x * 8 + (threadIdx.x >> 5);
    if (node >= NN) return;
    int lane = threadIdx.x & 31;
    int beg = g_rowptr[node], end = g_rowptr[node + 1];
    float4 er = *(const float4*)(g_er + (size_t)node * 4);

    // pass 1
    float4 s = make_float4(0.f, 0.f, 0.f, 0.f);
    for (int i = beg + lane; i < end; i += 32) {
        int src = g_csr_src[i];
        int eid = g_csr_eid[i];
        float4 l = *(const float4*)(g_el + (size_t)src * 4);
        float z0 = lrelu(l.x + er.x), z1 = lrelu(l.y + er.y);
        float z2 = lrelu(l.z + er.z), z3 = lrelu(l.w + er.w);
        atten[eid] = 0.25f * (z0 + z1 + z2 + z3);
        if (LAYER == 1)
            *(float4*)(e1 + (size_t)eid * 4) = make_float4(z0, z1, z2, z3);
        float4 wv = make_float4(__expf(z0), __expf(z1), __expf(z2), __expf(z3));
        *(float4*)(g_w + (size_t)i * 4) = wv;
        s.x += wv.x; s.y += wv.y; s.z += wv.z; s.w += wv.w;
    }
    __syncwarp();
#pragma unroll
    for (int o = 16; o; o >>= 1) {
        s.x += __shfl_xor_sync(0xffffffffu, s.x, o);
        s.y += __shfl_xor_sync(0xffffffffu, s.y, o);
        s.z += __shfl_xor_sync(0xffffffffu, s.z, o);
        s.w += __shfl_xor_sync(0xffffffffu, s.w, o);
    }

    int h = lane >> 3;
    float dh = (h == 0) ? s.x : (h == 1) ? s.y : (h == 2) ? s.z : s.w;
    float inv = dh > 0.f ? 1.f / dh : 0.f;

    // pass 2 (unroll 4)
    float4 acc = make_float4(0.f, 0.f, 0.f, 0.f);
    int i = beg;
    for (; i + 4 <= end; i += 4) {
        int s0 = g_csr_src[i], s1 = g_csr_src[i + 1];
        int s2 = g_csr_src[i + 2], s3 = g_csr_src[i + 3];
        float a0 = g_w[(size_t)i * 4 + h] * inv;
        float a1 = g_w[(size_t)(i + 1) * 4 + h] * inv;
        float a2 = g_w[(size_t)(i + 2) * 4 + h] * inv;
        float a3 = g_w[(size_t)(i + 3) * 4 + h] * inv;
        float4 f0 = *(const float4*)(feat + (size_t)s0 * HD + lane * 4);
        float4 f1 = *(const float4*)(feat + (size_t)s1 * HD + lane * 4);
        float4 f2 = *(const float4*)(feat + (size_t)s2 * HD + lane * 4);
        float4 f3 = *(const float4*)(feat + (size_t)s3 * HD + lane * 4);
        acc.x += f0.x * a0 + f1.x * a1 + f2.x * a2 + f3.x * a3;
        acc.y += f0.y * a0 + f1.y * a1 + f2.y * a2 + f3.y * a3;
        acc.z += f0.z * a0 + f1.z * a1 + f2.z * a2 + f3.z * a3;
        acc.w += f0.w * a0 + f1.w * a1 + f2.w * a2 + f3.w * a3;
    }
    for (; i < end; i++) {
        int s0 = g_csr_src[i];
        float a0 = g_w[(size_t)i * 4 + h] * inv;
        float4 f0 = *(const float4*)(feat + (size_t)s0 * HD + lane * 4);
        acc.x += f0.x * a0; acc.y += f0.y * a0;
        acc.z += f0.z * a0; acc.w += f0.w * a0;
    }

    if (LAYER == 0) {
        acc.x = elu1(acc.x); acc.y = elu1(acc.y);
        acc.z = elu1(acc.z); acc.w = elu1(acc.w);
        *(float4*)(out + (size_t)node * HD + lane * 4) = acc;  // out = g_h1
    } else {
        float4 r = *(const float4*)(g_h1 + (size_t)node * HD + lane * 4);
        acc.x = elu1(acc.x + r.x); acc.y = elu1(acc.y + r.y);
        acc.z = elu1(acc.z + r.z); acc.w = elu1(acc.w + r.w);
        *(float4*)(out + (size_t)node * HD + lane * 4) = acc;  // temp [N,128]
        int d = (lane * 4) & 31;
        float* headp = out + (size_t)NN * HD + (size_t)h * NN * D + (size_t)node * D + d;
        *(float4*)headp = acc;
    }
}

static inline int cdiv(int a, int b) { return (a + b - 1) / b; }

extern "C" void kernel_launch(void* const* d_in, const int* in_sizes, int n_in,
                              void* d_out, int out_size) {
    const float* x   = (const float*)d_in[0];
    const int*   ei  = (const int*)d_in[1];
    const float* W0  = (const float*)d_in[2];
    const float* al0 = (const float*)d_in[3];
    const float* ar0 = (const float*)d_in[4];
    const float* W1  = (const float*)d_in[5];
    const float* al1 = (const float*)d_in[6];
    const float* ar1 = (const float*)d_in[7];
    float* out = (float*)d_out;

    float* e1_out = out + (size_t)NN * HD + (size_t)H * NN * D;  // [E, H]
    float* atten0 = e1_out + (size_t)EE * H;                     // [E]
    float* atten1 = atten0 + EE;                                 // [E]

    void *p_feat, *p_h1;
    cudaGetSymbolAddress(&p_feat, g_feat);
    cudaGetSymbolAddress(&p_h1, g_h1);
    float* feat = (float*)p_feat;
    float* h1   = (float*)p_h1;

    const int T = 256;
    int g_gemm = cdiv(NN, 128);
    int g_edge = cdiv(EE, T);
    int g_node = cdiv(NN, 8);

    cudaStream_t sA;
    cudaStreamCreateWithFlags(&sA, cudaStreamNonBlocking);
    cudaEvent_t evFork, evCsr, evH1;
    cudaEventCreateWithFlags(&evFork, cudaEventDisableTiming);
    cudaEventCreateWithFlags(&evCsr, cudaEventDisableTiming);
    cudaEventCreateWithFlags(&evH1, cudaEventDisableTiming);

    // ---- fork: CSR build on sA, concurrent with layer-0 GEMM ----
    cudaEventRecord(evFork, 0);
    cudaStreamWaitEvent(sA, evFork, 0);
    count_deg_kernel<<<g_edge, T, 0, sA>>>(ei);                      // 1
    scan1_kernel<<<NBLK1, SCAN_BS, 0, sA>>>();                       // 2
    scan2_kernel<<<1, 256, 0, sA>>>();                               // 3
    sgemm_tf32<<<g_gemm, T>>>(x, W0, al0, ar0, feat, NN, IN_DIM);    // 4 <- profiled
    scan3_kernel<<<NBLK1, SCAN_BS, 0, sA>>>();                       // 5
    fill_csr_kernel<<<g_edge, T, 0, sA>>>(ei);                       // 6
    cudaEventRecord(evCsr, sA);

    // ---- join: node_agg<0> needs GEMM0 (main) + CSR (sA) ----
    cudaStreamWaitEvent(0, evCsr, 0);
    node_agg_kernel<0><<<g_node, T>>>(feat, h1, atten0, nullptr);    // 7
    cudaEventRecord(evH1, 0);

    // ---- layer 1 ----
    sgemm_tf32<<<g_gemm, T>>>(h1, W1, al1, ar1, feat, NN, HD);       // 8
    node_agg_kernel<1><<<g_node, T>>>(feat, out, atten1, e1_out);    // 9
}

// round 16
// speedup vs baseline: 1.4942x; 1.0986x over previous
#include <cuda_runtime.h>
#include <cstdint>

#define NN 100000
#define EE 800000
#define IN_DIM 256
#define H 4
#define D 32
#define HD 128
#define SLOPE 0.2f

// ---------------- scratch (no allocations allowed) ----------------
__device__ float g_feat[NN * HD];     // projected features of current layer
__device__ float g_h1[NN * HD];       // layer-0 output (residual for layer 1)
__device__ float g_el[NN * H];        // layer-0 attention dots
__device__ float g_er[NN * H];
__device__ float g_el2[NN * H];       // layer-1 attention dots
__device__ float g_er2[NN * H];
__device__ float g_w[EE * H];         // exp(score) in CSR order
__device__ int   g_deg[NN];           // zero at load; re-zeroed by scan3
__device__ int   g_rowptr[NN + 1];
__device__ int   g_cursor[NN];
__device__ int   g_partial[256];
__device__ int   g_csr_src[EE];

__device__ __forceinline__ float elu1(float x) {
    return x > 0.f ? x : expm1f(x);
}
__device__ __forceinline__ float tf32r(float x) {
    uint32_t u;
    asm("cvt.rna.tf32.f32 %0, %1;" : "=r"(u) : "f"(x));
    return __uint_as_float(u);
}
__device__ __forceinline__ float lrelu(float x) {
    return x > 0.f ? x : SLOPE * x;
}

// ================= CSR build =================
__global__ void count_deg_kernel(const int* __restrict__ ei) {
    int e = blockIdx.x * blockDim.x + threadIdx.x;
    if (e < EE) atomicAdd(&g_deg[ei[EE + e]], 1);
}

#define SCAN_BS 512
#define NBLK1 ((NN + SCAN_BS - 1) / SCAN_BS)   // 196

__global__ __launch_bounds__(SCAN_BS) void scan1_kernel() {
    __shared__ int s[SCAN_BS];
    int t = threadIdx.x;
    int i = blockIdx.x * SCAN_BS + t;
    int v = (i < NN) ? g_deg[i] : 0;
    s[t] = v;
    __syncthreads();
#pragma unroll
    for (int off = 1; off < SCAN_BS; off <<= 1) {
        int x = (t >= off) ? s[t - off] : 0;
        __syncthreads();
        s[t] += x;
        __syncthreads();
    }
    if (i < NN) g_rowptr[i] = s[t] - v;
    if (t == SCAN_BS - 1) g_partial[blockIdx.x] = s[t];
}

__global__ __launch_bounds__(256) void scan2_kernel() {
    __shared__ int s[256];
    int t = threadIdx.x;
    int v = (t < NBLK1) ? g_partial[t] : 0;
    s[t] = v;
    __syncthreads();
#pragma unroll
    for (int off = 1; off < 256; off <<= 1) {
        int x = (t >= off) ? s[t - off] : 0;
        __syncthreads();
        s[t] += x;
        __syncthreads();
    }
    if (t < NBLK1) g_partial[t] = s[t] - v;
}

__global__ __launch_bounds__(SCAN_BS) void scan3_kernel() {
    int t = threadIdx.x;
    int i = blockIdx.x * SCAN_BS + t;
    if (i < NN) {
        int r = g_rowptr[i] + g_partial[blockIdx.x];
        g_rowptr[i] = r;
        g_cursor[i] = r;
        g_deg[i] = 0;                        // re-zero for next replay
    }
    if (i == 0) g_rowptr[NN] = EE;
}

__global__ void fill_csr_kernel(const int* __restrict__ ei) {
    int e = blockIdx.x * blockDim.x + threadIdx.x;
    if (e >= EE) return;
    int s = ei[e], d = ei[EE + e];
    int pos = atomicAdd(&g_cursor[d], 1);
    g_csr_src[pos] = s;
}

// ========== TF32 tensor-core GEMM fused with attention dots ==========
#define AS_S 20
#define BS_S 136

__global__ __launch_bounds__(256, 2) void sgemm_tf32(const float* __restrict__ A,
                                                     const float* __restrict__ B,
                                                     const float* __restrict__ al,
                                                     const float* __restrict__ ar,
                                                     float* __restrict__ C,
                                                     float* __restrict__ elo,
                                                     float* __restrict__ ero,
                                                     int M, int K) {
    __shared__ float As[2][128][AS_S];
    __shared__ float Bs[2][16][BS_S];
    int tid = threadIdx.x;
    int lane = tid & 31;
    int wid = tid >> 5;
    int warp_m = wid & 1;
    int warp_n = wid >> 1;
    int block_row = blockIdx.x * 128;

    float c[4][4][4];
#pragma unroll
    for (int i = 0; i < 4; i++)
#pragma unroll
        for (int j = 0; j < 4; j++)
#pragma unroll
            for (int k = 0; k < 4; k++) c[i][j][k] = 0.f;

    int ar_r = tid >> 2;
    int ac = (tid & 3) * 4;
    int br = tid >> 5;
    int bc = (tid & 31) * 4;

    int gr0 = block_row + ar_r;
    int gr1 = gr0 + 64;
    bool v0 = gr0 < M, v1 = gr1 < M;
    const float* Ap0 = A + (size_t)gr0 * K;
    const float* Ap1 = A + (size_t)gr1 * K;

    int ntiles = K >> 4;
    float4 pa0, pa1, pb0, pb1;
    {
        pa0 = v0 ? *(const float4*)(Ap0 + ac) : make_float4(0, 0, 0, 0);
        pa1 = v1 ? *(const float4*)(Ap1 + ac) : make_float4(0, 0, 0, 0);
        pb0 = *(const float4*)(B + (size_t)br * 128 + bc);
        pb1 = *(const float4*)(B + (size_t)(br + 8) * 128 + bc);
        float* as0 = &As[0][ar_r][ac];
        as0[0] = tf32r(pa0.x); as0[1] = tf32r(pa0.y);
        as0[2] = tf32r(pa0.z); as0[3] = tf32r(pa0.w);
        float* as1 = &As[0][ar_r + 64][ac];
        as1[0] = tf32r(pa1.x); as1[1] = tf32r(pa1.y);
        as1[2] = tf32r(pa1.z); as1[3] = tf32r(pa1.w);
        float* bs0 = &Bs[0][br][bc];
        bs0[0] = tf32r(pb0.x); bs0[1] = tf32r(pb0.y);
        bs0[2] = tf32r(pb0.z); bs0[3] = tf32r(pb0.w);
        float* bs1 = &Bs[0][br + 8][bc];
        bs1[0] = tf32r(pb1.x); bs1[1] = tf32r(pb1.y);
        bs1[2] = tf32r(pb1.z); bs1[3] = tf32r(pb1.w);
    }
    __syncthreads();

    int buf = 0;
    for (int kt = 0; kt < ntiles; kt++) {
        bool more = (kt + 1) < ntiles;
        if (more) {
            int kb = (kt + 1) * 16;
            pa0 = v0 ? *(const float4*)(Ap0 + kb + ac) : make_float4(0, 0, 0, 0);
            pa1 = v1 ? *(const float4*)(Ap1 + kb + ac) : make_float4(0, 0, 0, 0);
            pb0 = *(const float4*)(B + (size_t)(kb + br) * 128 + bc);
            pb1 = *(const float4*)(B + (size_t)(kb + br + 8) * 128 + bc);
        }
#pragma unroll
        for (int ks = 0; ks < 2; ks++) {
            int k8 = ks * 8;
            uint32_t af[4][4];
            uint32_t bf[4][2];
#pragma unroll
            for (int mi = 0; mi < 4; mi++) {
                int r = warp_m * 64 + mi * 16 + (lane >> 2);
                int kc = k8 + (lane & 3);
                af[mi][0] = __float_as_uint(As[buf][r][kc]);
                af[mi][1] = __float_as_uint(As[buf][r + 8][kc]);
                af[mi][2] = __float_as_uint(As[buf][r][kc + 4]);
                af[mi][3] = __float_as_uint(As[buf][r + 8][kc + 4]);
            }
#pragma unroll
            for (int nj = 0; nj < 4; nj++) {
                int cc = warp_n * 32 + nj * 8 + (lane >> 2);
                int kr = k8 + (lane & 3);
                bf[nj][0] = __float_as_uint(Bs[buf][kr][cc]);
                bf[nj][1] = __float_as_uint(Bs[buf][kr + 4][cc]);
            }
#pragma unroll
            for (int mi = 0; mi < 4; mi++)
#pragma unroll
                for (int nj = 0; nj < 4; nj++) {
                    asm("mma.sync.aligned.m16n8k8.row.col.f32.tf32.tf32.f32 "
                        "{%0,%1,%2,%3}, {%4,%5,%6,%7}, {%8,%9}, {%0,%1,%2,%3};"
                        : "+f"(c[mi][nj][0]), "+f"(c[mi][nj][1]),
                          "+f"(c[mi][nj][2]), "+f"(c[mi][nj][3])
                        : "r"(af[mi][0]), "r"(af[mi][1]),
                          "r"(af[mi][2]), "r"(af[mi][3]),
                          "r"(bf[nj][0]), "r"(bf[nj][1]));
                }
        }
        if (more) {
            int nb = buf ^ 1;
            float* as0 = &As[nb][ar_r][ac];
            as0[0] = tf32r(pa0.x); as0[1] = tf32r(pa0.y);
            as0[2] = tf32r(pa0.z); as0[3] = tf32r(pa0.w);
            float* as1 = &As[nb][ar_r + 64][ac];
            as1[0] = tf32r(pa1.x); as1[1] = tf32r(pa1.y);
            as1[2] = tf32r(pa1.z); as1[3] = tf32r(pa1.w);
            float* bs0 = &Bs[nb][br][bc];
            bs0[0] = tf32r(pb0.x); bs0[1] = tf32r(pb0.y);
            bs0[2] = tf32r(pb0.z); bs0[3] = tf32r(pb0.w);
            float* bs1 = &Bs[nb][br + 8][bc];
            bs1[0] = tf32r(pb1.x); bs1[1] = tf32r(pb1.y);
            bs1[2] = tf32r(pb1.z); bs1[3] = tf32r(pb1.w);
        }
        __syncthreads();
        buf ^= 1;
    }

    float alv[8], arv[8];
#pragma unroll
    for (int nj = 0; nj < 4; nj++) {
#pragma unroll
        for (int t = 0; t < 2; t++) {
            int col = warp_n * 32 + nj * 8 + (lane & 3) * 2 + t;
            alv[nj * 2 + t] = al[col];
            arv[nj * 2 + t] = ar[col];
        }
    }

#pragma unroll
    for (int mi = 0; mi < 4; mi++) {
        float sl0 = 0.f, sl1 = 0.f, sr0 = 0.f, sr1 = 0.f;
#pragma unroll
        for (int nj = 0; nj < 4; nj++) {
            int row0 = block_row + warp_m * 64 + mi * 16 + (lane >> 2);
            int col = warp_n * 32 + nj * 8 + (lane & 3) * 2;
            if (row0 < M)
                *(float2*)(C + (size_t)row0 * 128 + col) =
                    make_float2(c[mi][nj][0], c[mi][nj][1]);
            int row1 = row0 + 8;
            if (row1 < M)
                *(float2*)(C + (size_t)row1 * 128 + col) =
                    make_float2(c[mi][nj][2], c[mi][nj][3]);
            sl0 += c[mi][nj][0] * alv[nj * 2] + c[mi][nj][1] * alv[nj * 2 + 1];
            sl1 += c[mi][nj][2] * alv[nj * 2] + c[mi][nj][3] * alv[nj * 2 + 1];
            sr0 += c[mi][nj][0] * arv[nj * 2] + c[mi][nj][1] * arv[nj * 2 + 1];
            sr1 += c[mi][nj][2] * arv[nj * 2] + c[mi][nj][3] * arv[nj * 2 + 1];
        }
#pragma unroll
        for (int o = 1; o <= 2; o <<= 1) {
            sl0 += __shfl_xor_sync(0xffffffffu, sl0, o);
            sl1 += __shfl_xor_sync(0xffffffffu, sl1, o);
            sr0 += __shfl_xor_sync(0xffffffffu, sr0, o);
            sr1 += __shfl_xor_sync(0xffffffffu, sr1, o);
        }
        if ((lane & 3) == 0) {
            int row0 = block_row + warp_m * 64 + mi * 16 + (lane >> 2);
            int row1 = row0 + 8;
            if (row0 < M) {
                elo[(size_t)row0 * 4 + warp_n] = sl0;
                ero[(size_t)row0 * 4 + warp_n] = sr0;
            }
            if (row1 < M) {
                elo[(size_t)row1 * 4 + warp_n] = sl1;
                ero[(size_t)row1 * 4 + warp_n] = sr1;
            }
        }
    }
}

// ------ edge outputs in ORIGINAL edge order (coalesced writes) ----------
template <int WITH_E1>
__global__ void edge_out_kernel(const int* __restrict__ ei,
                                const float* __restrict__ el,
                                const float* __restrict__ erp,
                                float* __restrict__ atten,
                                float* __restrict__ e1) {
    int e = blockIdx.x * blockDim.x + threadIdx.x;
    if (e >= EE) return;
    int s = ei[e], d = ei[EE + e];
    float4 l = *(const float4*)(el + (size_t)s * 4);
    float4 r = *(const float4*)(erp + (size_t)d * 4);
    float z0 = lrelu(l.x + r.x), z1 = lrelu(l.y + r.y);
    float z2 = lrelu(l.z + r.z), z3 = lrelu(l.w + r.w);
    atten[e] = 0.25f * (z0 + z1 + z2 + z3);
    if (WITH_E1)
        *(float4*)(e1 + (size_t)e * 4) = make_float4(z0, z1, z2, z3);
}

// ------ warp-per-node: inline scores (lane-parallel) + w + agg ----------
// pass 1 (lane-strided): z = lrelu(el[src]+er[node]); w=exp(z); denom.
// pass 2 (warp-serial, unroll-2): a = w[i]*inv, gather feat[src].
template <int LAYER>
__global__ __launch_bounds__(256) void node_agg_kernel(const float* __restrict__ feat,
                                                       const float* __restrict__ el,
                                                       const float* __restrict__ erp,
                                                       float* __restrict__ out) {
    int node = blockIdx.x * 8 + (threadIdx.x >> 5);
    if (node >= NN) return;
    int lane = threadIdx.x & 31;
    int beg = g_rowptr[node], end = g_rowptr[node + 1];
    float4 er = *(const float4*)(erp + (size_t)node * 4);

    // pass 1
    float4 s = make_float4(0.f, 0.f, 0.f, 0.f);
    for (int i = beg + lane; i < end; i += 32) {
        int src = g_csr_src[i];
        float4 l = *(const float4*)(el + (size_t)src * 4);
        float z0 = lrelu(l.x + er.x), z1 = lrelu(l.y + er.y);
        float z2 = lrelu(l.z + er.z), z3 = lrelu(l.w + er.w);
        float4 wv = make_float4(__expf(z0), __expf(z1), __expf(z2), __expf(z3));
        *(float4*)(g_w + (size_t)i * 4) = wv;
        s.x += wv.x; s.y += wv.y; s.z += wv.z; s.w += wv.w;
    }
    __syncwarp();
#pragma unroll
    for (int o = 16; o; o >>= 1) {
        s.x += __shfl_xor_sync(0xffffffffu, s.x, o);
        s.y += __shfl_xor_sync(0xffffffffu, s.y, o);
        s.z += __shfl_xor_sync(0xffffffffu, s.z, o);
        s.w += __shfl_xor_sync(0xffffffffu, s.w, o);
    }

    int h = lane >> 3;
    float dh = (h == 0) ? s.x : (h == 1) ? s.y : (h == 2) ? s.z : s.w;
    float inv = dh > 0.f ? 1.f / dh : 0.f;

    // pass 2 (unroll 2 — R12-proven)
    float4 acc = make_float4(0.f, 0.f, 0.f, 0.f);
    int i = beg;
    for (; i + 2 <= end; i += 2) {
        int s0 = g_csr_src[i], s1 = g_csr_src[i + 1];
        float a0 = g_w[(size_t)i * 4 + h] * inv;
        float a1 = g_w[(size_t)(i + 1) * 4 + h] * inv;
        float4 f0 = *(const float4*)(feat + (size_t)s0 * HD + lane * 4);
        float4 f1 = *(const float4*)(feat + (size_t)s1 * HD + lane * 4);
        acc.x += f0.x * a0 + f1.x * a1;
        acc.y += f0.y * a0 + f1.y * a1;
        acc.z += f0.z * a0 + f1.z * a1;
        acc.w += f0.w * a0 + f1.w * a1;
    }
    if (i < end) {
        int s0 = g_csr_src[i];
        float a0 = g_w[(size_t)i * 4 + h] * inv;
        float4 f0 = *(const float4*)(feat + (size_t)s0 * HD + lane * 4);
        acc.x += f0.x * a0; acc.y += f0.y * a0;
        acc.z += f0.z * a0; acc.w += f0.w * a0;
    }

    if (LAYER == 0) {
        acc.x = elu1(acc.x); acc.y = elu1(acc.y);
        acc.z = elu1(acc.z); acc.w = elu1(acc.w);
        *(float4*)(out + (size_t)node * HD + lane * 4) = acc;  // out = g_h1
    } else {
        float4 r = *(const float4*)(g_h1 + (size_t)node * HD + lane * 4);
        acc.x = elu1(acc.x + r.x); acc.y = elu1(acc.y + r.y);
        acc.z = elu1(acc.z + r.z); acc.w = elu1(acc.w + r.w);
        *(float4*)(out + (size_t)node * HD + lane * 4) = acc;  // temp [N,128]
        int d = (lane * 4) & 31;
        float* headp = out + (size_t)NN * HD + (size_t)h * NN * D + (size_t)node * D + d;
        *(float4*)headp = acc;
    }
}

static inline int cdiv(int a, int b) { return (a + b - 1) / b; }

extern "C" void kernel_launch(void* const* d_in, const int* in_sizes, int n_in,
                              void* d_out, int out_size) {
    const float* x   = (const float*)d_in[0];
    const int*   ei  = (const int*)d_in[1];
    const float* W0  = (const float*)d_in[2];
    const float* al0 = (const float*)d_in[3];
    const float* ar0 = (const float*)d_in[4];
    const float* W1  = (const float*)d_in[5];
    const float* al1 = (const float*)d_in[6];
    const float* ar1 = (const float*)d_in[7];
    float* out = (float*)d_out;

    float* e1_out = out + (size_t)NN * HD + (size_t)H * NN * D;  // [E, H]
    float* atten0 = e1_out + (size_t)EE * H;                     // [E]
    float* atten1 = atten0 + EE;                                 // [E]

    void *p_feat, *p_h1, *p_el, *p_er, *p_el2, *p_er2;
    cudaGetSymbolAddress(&p_feat, g_feat);
    cudaGetSymbolAddress(&p_h1, g_h1);
    cudaGetSymbolAddress(&p_el, g_el);
    cudaGetSymbolAddress(&p_er, g_er);
    cudaGetSymbolAddress(&p_el2, g_el2);
    cudaGetSymbolAddress(&p_er2, g_er2);
    float* feat = (float*)p_feat;
    float* h1   = (float*)p_h1;
    float* el   = (float*)p_el;
    float* er   = (float*)p_er;
    float* el2  = (float*)p_el2;
    float* er2  = (float*)p_er2;

    const int T = 256;
    int g_gemm = cdiv(NN, 128);
    int g_edge = cdiv(EE, T);
    int g_node = cdiv(NN, 8);

    cudaStream_t sA;
    cudaStreamCreateWithFlags(&sA, cudaStreamNonBlocking);
    cudaEvent_t evFork, evCsr, evNA0, evG1, evOut1;
    cudaEventCreateWithFlags(&evFork, cudaEventDisableTiming);
    cudaEventCreateWithFlags(&evCsr, cudaEventDisableTiming);
    cudaEventCreateWithFlags(&evNA0, cudaEventDisableTiming);
    cudaEventCreateWithFlags(&evG1, cudaEventDisableTiming);
    cudaEventCreateWithFlags(&evOut1, cudaEventDisableTiming);

    // ---- fork: CSR build on sA, concurrent with layer-0 GEMM ----
    cudaEventRecord(evFork, 0);
    cudaStreamWaitEvent(sA, evFork, 0);
    count_deg_kernel<<<g_edge, T, 0, sA>>>(ei);                          // 1
    scan1_kernel<<<NBLK1, SCAN_BS, 0, sA>>>();                           // 2
    scan2_kernel<<<1, 256, 0, sA>>>();                                   // 3
    sgemm_tf32<<<g_gemm, T>>>(x, W0, al0, ar0, feat, el, er,
                              NN, IN_DIM);                               // 4 <- profiled
    scan3_kernel<<<NBLK1, SCAN_BS, 0, sA>>>();                           // 5
    fill_csr_kernel<<<g_edge, T, 0, sA>>>(ei);                           // 6
    cudaEventRecord(evCsr, sA);

    // ---- join: node_agg<0> needs GEMM0 (main) + CSR (sA) ----
    cudaStreamWaitEvent(0, evCsr, 0);
    node_agg_kernel<0><<<g_node, T>>>(feat, el, er, h1);                 // 7
    cudaEventRecord(evNA0, 0);

    // ---- edge_out0 on sA (reads el/er) ∥ GEMM1 on main (writes el2/er2) --
    cudaStreamWaitEvent(sA, evNA0, 0);
    edge_out_kernel<0><<<g_edge, T, 0, sA>>>(ei, el, er, atten0, nullptr); // 8

    sgemm_tf32<<<g_gemm, T>>>(h1, W1, al1, ar1, feat, el2, er2,
                              NN, HD);                                   // 9
    cudaEventRecord(evG1, 0);

    // ---- edge_out1 on sA ∥ node_agg<1> on main ----
    cudaStreamWaitEvent(sA, evG1, 0);
    edge_out_kernel<1><<<g_edge, T, 0, sA>>>(ei, el2, er2, atten1, e1_out); // 10
    cudaEventRecord(evOut1, sA);

    node_agg_kernel<1><<<g_node, T>>>(feat, el2, er2, out);              // 11
    cudaStreamWaitEvent(0, evOut1, 0);
}